// round 14
// baseline (speedup 1.0000x reference)
#include <cuda_runtime.h>
#include <cuda_fp16.h>
#include <cstdint>

#define NP 16384      // number of z vectors (16*32*32)
#define NC 8192       // codebook size
#define DIM 256       // embedding dim
#define DECAYF 0.99f
#define OMDECAYF 0.01f
#define EPSF 1e-5f
#define MARGIN 6.0f
#define CAND_CAP 1024

// GEMM tiling: BM=256, BN=128, 16 warps (4x4), warp tile 64x32, fp16 accum (R11 geometry)
#define BM 256
#define BN 128
#define BK 32
#define NCHUNK (DIM / BK)      // 8
#define STAGES 3
#define ROWB 80
#define A_TILE_B (BM * ROWB)   // 20480
#define B_TILE_B (BN * ROWB)   // 10240
#define STAGE_B (A_TILE_B + B_TILE_B)   // 30720
#define NTHREADS 512

// ---------------- scratch (no allocation allowed) ----------------
__device__ unsigned long long g_best[NP];
__device__ int g_ccount[NP];
__device__ unsigned g_cand[(size_t)NP * CAND_CAP];  // (maph16(score)<<16)|col
__device__ float g_wnorm[NC];
__device__ float g_counts[NC];
__device__ float g_ptloss[NP];
__device__ float g_n;
__device__ __align__(256) __half g_zh[NP * DIM];
__device__ __align__(256) __half g_wh[NC * DIM];

// ---------------- PTX helpers ----------------
__device__ __forceinline__ uint32_t smem_u32(const void* p) {
    uint32_t a;
    asm("{ .reg .u64 t; cvta.to.shared.u64 t, %1; cvt.u32.u64 %0, t; }" : "=r"(a) : "l"(p));
    return a;
}
__device__ __forceinline__ void cp16(uint32_t dst, const void* src) {
    asm volatile("cp.async.cg.shared.global [%0], [%1], 16;" :: "r"(dst), "l"(src) : "memory");
}
#define CP_COMMIT() asm volatile("cp.async.commit_group;" ::: "memory")
#define CP_WAIT1()  asm volatile("cp.async.wait_group 1;" ::: "memory")
#define CP_WAIT0()  asm volatile("cp.async.wait_group 0;" ::: "memory")

__device__ __forceinline__ void ldm_x4(uint32_t* r, uint32_t addr) {
    asm volatile("ldmatrix.sync.aligned.m8n8.x4.shared.b16 {%0,%1,%2,%3}, [%4];"
        : "=r"(r[0]), "=r"(r[1]), "=r"(r[2]), "=r"(r[3]) : "r"(addr));
}
__device__ __forceinline__ void mma16816h(uint32_t* c, const uint32_t* a, const uint32_t* b) {
    asm volatile(
        "mma.sync.aligned.m16n8k16.row.col.f16.f16.f16.f16 "
        "{%0,%1}, {%2,%3,%4,%5}, {%6,%7}, {%0,%1};"
        : "+r"(c[0]), "+r"(c[1])
        : "r"(a[0]), "r"(a[1]), "r"(a[2]), "r"(a[3]), "r"(b[0]), "r"(b[1]));
}
__device__ __forceinline__ unsigned mapf(float f) {
    unsigned u = __float_as_uint(f);
    return (u & 0x80000000u) ? ~u : (u | 0x80000000u);
}
__device__ __forceinline__ float unmapf(unsigned v) {
    return __uint_as_float((v & 0x80000000u) ? (v & 0x7FFFFFFFu) : ~v);
}
__device__ __forceinline__ unsigned maph16(unsigned short h) {
    return (h & 0x8000u) ? (unsigned)(~h & 0xFFFFu) : (unsigned)(h | 0x8000u);
}
__device__ __forceinline__ float unmaph16(unsigned v) {
    unsigned short h = (v & 0x8000u) ? (unsigned short)(v & 0x7FFFu)
                                     : (unsigned short)(~v & 0xFFFFu);
    return __half2float(__ushort_as_half(h));
}

// ---------------- K0: prep — init + fp16 conversion (merged) ----------------
__global__ void prep_kernel(const float* __restrict__ z, const float* __restrict__ w,
                            const float* __restrict__ ea_in, float* __restrict__ out_ea) {
    int i = blockIdx.x * blockDim.x + threadIdx.x;
    if (i < NP * DIM) g_zh[i] = __float2half_rn(z[i]);
    if (i < NC * DIM) {
        g_wh[i] = __float2half_rn(w[i]);
        out_ea[i] = DECAYF * ea_in[i];
    }
    if (i < NP) g_ccount[i] = 0;
    if (i < NC) g_counts[i] = 0.f;
}

// ---------------- K1: per-code squared norms (fp32 exact) ----------------
__global__ void wnorm_kernel(const float* __restrict__ w) {
    int warp = (blockIdx.x * blockDim.x + threadIdx.x) >> 5;
    int lane = threadIdx.x & 31;
    if (warp >= NC) return;
    const float4* row = (const float4*)(w + (size_t)warp * DIM);
    float s = 0.f;
#pragma unroll
    for (int it = 0; it < 2; it++) {
        float4 v = row[lane + it * 32];
        s += v.x * v.x + v.y * v.y + v.z * v.z + v.w * v.w;
    }
#pragma unroll
    for (int off = 16; off; off >>= 1) s += __shfl_xor_sync(0xffffffffu, s, off);
    if (lane == 0) g_wnorm[warp] = s;
}

// ---------------- K2: fp16-acc mma GEMM + in-place prune/append ----------------
__global__ __launch_bounds__(NTHREADS, 1) void mma_gemm_approx() {
    extern __shared__ char smem[];
    const uint32_t sb = smem_u32(smem);
    const int tid = threadIdx.x, wid = tid >> 5, lane = tid & 31;
    const int warp_m = wid >> 2, warp_n = wid & 3;   // 4 x 4 warps
    const int m0 = blockIdx.x * BM, n0 = blockIdx.y * BN;

    unsigned* rowmin = (unsigned*)smem;              // 256 u32 @ [0,1024)
    float* wns = (float*)(smem + 1024);              // 128 f32 @ [1024,1536)
    constexpr uint32_t OFF_STAGE = 2048;

    if (tid < BM) rowmin[tid] = 0xFFFFFFFFu;
    if (tid < BN) wns[tid] = g_wnorm[n0 + tid];

    auto load_stage = [&](int chunk, int stg) {
        const uint32_t stage = sb + OFF_STAGE + stg * STAGE_B;
#pragma unroll
        for (int r = 0; r < 3; r++) {
            int idx = tid + r * NTHREADS;
            if (idx < 1024) {
                int row = idx >> 2, cj = idx & 3;
                const __half* src = g_zh + (size_t)(m0 + row) * DIM + chunk * BK + cj * 8;
                cp16(stage + row * ROWB + cj * 16, src);
            } else {
                int q = idx - 1024;
                int row = q >> 2, cj = q & 3;
                const __half* src = g_wh + (size_t)(n0 + row) * DIM + chunk * BK + cj * 8;
                cp16(stage + A_TILE_B + row * ROWB + cj * 16, src);
            }
        }
    };

    load_stage(0, 0); CP_COMMIT();
    load_stage(1, 1); CP_COMMIT();

    uint32_t c[4][4][2] = {};    // [mt][nt][2]  fp16x2 accum, 64x32 warp tile

    for (int ch = 0; ch < NCHUNK; ch++) {
        if (ch == NCHUNK - 1) { CP_WAIT0(); } else { CP_WAIT1(); }
        __syncthreads();
        if (ch + 2 < NCHUNK) { load_stage(ch + 2, (ch + 2) % STAGES); CP_COMMIT(); }

        const uint32_t stage = sb + OFF_STAGE + (ch % STAGES) * STAGE_B;
        const uint32_t sA = stage, sB = stage + A_TILE_B;

#pragma unroll
        for (int s = 0; s < 2; s++) {
            const uint32_t acol = s * 32 + ((lane >> 4) << 4);
            const int arow = lane & 15;
            uint32_t ah[4][4];
#pragma unroll
            for (int mt = 0; mt < 4; mt++)
                ldm_x4(ah[mt], sA + (uint32_t)(warp_m * 64 + mt * 16 + arow) * ROWB + acol);
            const int brow = ((lane >> 4) << 3) + (lane & 7);
            const uint32_t bcol = s * 32 + ((lane >> 3) & 1) * 16;
            uint32_t bh[2][4];
#pragma unroll
            for (int nt2 = 0; nt2 < 2; nt2++)
                ldm_x4(bh[nt2], sB + (uint32_t)(warp_n * 32 + nt2 * 16 + brow) * ROWB + bcol);
#pragma unroll
            for (int mt = 0; mt < 4; mt++)
#pragma unroll
                for (int nt = 0; nt < 4; nt++)
                    mma16816h(c[mt][nt], ah[mt], &bh[nt >> 1][(nt & 1) * 2]);
        }
    }

    // ---- epilogue pass A: per-row minima of this tile into smem ----
    const int rbase = warp_m * 64 + (lane >> 2);
    const int lcol0 = warp_n * 32 + 2 * (lane & 3);
#pragma unroll
    for (int mt = 0; mt < 4; mt++) {
        const int r0 = rbase + mt * 16;
        unsigned best0 = 0xFFFFFFFFu, best1 = 0xFFFFFFFFu;
#pragma unroll
        for (int nt = 0; nt < 4; nt++) {
            const int col = lcol0 + nt * 8;
            float2 d0 = __half22float2(*(__half2*)&c[mt][nt][0]);
            float2 d1 = __half22float2(*(__half2*)&c[mt][nt][1]);
            float w0 = wns[col], w1 = wns[col + 1];
            best0 = min(best0, min(mapf(w0 - 2.f * d0.x), mapf(w1 - 2.f * d0.y)));
            best1 = min(best1, min(mapf(w0 - 2.f * d1.x), mapf(w1 - 2.f * d1.y)));
        }
#pragma unroll
        for (int off = 1; off < 4; off <<= 1) {
            best0 = min(best0, __shfl_xor_sync(0xffffffffu, best0, off));
            best1 = min(best1, __shfl_xor_sync(0xffffffffu, best1, off));
        }
        if ((lane & 3) == 0) {
            atomicMin(&rowmin[r0], best0);
            atomicMin(&rowmin[r0 + 8], best1);
        }
    }
    __syncthreads();

    // ---- epilogue pass B: append candidates <= tilemin + MARGIN ----
#pragma unroll
    for (int mt = 0; mt < 4; mt++) {
        const int r0 = rbase + mt * 16;
        const float t0 = unmapf(rowmin[r0]) + MARGIN;
        const float t1 = unmapf(rowmin[r0 + 8]) + MARGIN;
#pragma unroll
        for (int nt = 0; nt < 4; nt++) {
            const int col = lcol0 + nt * 8;
            float2 d0 = __half22float2(*(__half2*)&c[mt][nt][0]);
            float2 d1 = __half22float2(*(__half2*)&c[mt][nt][1]);
            float w0 = wns[col], w1 = wns[col + 1];
            float s00 = w0 - 2.f * d0.x, s01 = w1 - 2.f * d0.y;
            float s10 = w0 - 2.f * d1.x, s11 = w1 - 2.f * d1.y;
            if (s00 <= t0) {
                int p = atomicAdd(&g_ccount[m0 + r0], 1);
                if (p < CAND_CAP)
                    g_cand[(size_t)(m0 + r0) * CAND_CAP + p] =
                        (maph16(__half_as_ushort(__float2half_rn(s00))) << 16) | (unsigned)(n0 + col);
            }
            if (s01 <= t0) {
                int p = atomicAdd(&g_ccount[m0 + r0], 1);
                if (p < CAND_CAP)
                    g_cand[(size_t)(m0 + r0) * CAND_CAP + p] =
                        (maph16(__half_as_ushort(__float2half_rn(s01))) << 16) | (unsigned)(n0 + col + 1);
            }
            if (s10 <= t1) {
                int p = atomicAdd(&g_ccount[m0 + r0 + 8], 1);
                if (p < CAND_CAP)
                    g_cand[(size_t)(m0 + r0 + 8) * CAND_CAP + p] =
                        (maph16(__half_as_ushort(__float2half_rn(s10))) << 16) | (unsigned)(n0 + col);
            }
            if (s11 <= t1) {
                int p = atomicAdd(&g_ccount[m0 + r0 + 8], 1);
                if (p < CAND_CAP)
                    g_cand[(size_t)(m0 + r0 + 8) * CAND_CAP + p] =
                        (maph16(__half_as_ushort(__float2half_rn(s11))) << 16) | (unsigned)(n0 + col + 1);
            }
        }
    }
}

// ---------------- K3: refine — exact fp32 argmin over candidates ----------------
__global__ __launch_bounds__(256) void refine_kernel(const float* __restrict__ z,
                                                     const float* __restrict__ w) {
    const int tid = threadIdx.x, warp = tid >> 5, lane = tid & 31;
    const int m = blockIdx.x * 8 + warp;
    int cnt = g_ccount[m];
    if (cnt > CAND_CAP) cnt = CAND_CAP;
    const unsigned* clist = g_cand + (size_t)m * CAND_CAP;

    unsigned bestE = 0xFFFFFFFFu;
    for (int i = lane; i < cnt; i += 32) bestE = min(bestE, clist[i]);
#pragma unroll
    for (int off = 16; off; off >>= 1)
        bestE = min(bestE, __shfl_xor_sync(0xffffffffu, bestE, off));
    const float thr = unmaph16(bestE >> 16) + MARGIN;

    const float4* zp = (const float4*)(z + (size_t)m * DIM);
    const float4 z0 = zp[lane * 2], z1 = zp[lane * 2 + 1];
    unsigned long long best = 0xFFFFFFFFFFFFFFFFull;

    const int iters = (cnt + 31) >> 5;
    for (int e = 0; e < iters; e++) {
        int i = e * 32 + lane;
        unsigned entry = (i < cnt) ? clist[i] : 0xFFFFFFFFu;
        bool cand = (i < cnt) && (unmaph16(entry >> 16) <= thr);
        unsigned bal = __ballot_sync(0xffffffffu, cand);
        while (bal) {
            int src = __ffs(bal) - 1; bal &= bal - 1;
            unsigned ent = __shfl_sync(0xffffffffu, entry, src);
            int cc = (int)(ent & 0xFFFFu);
            const float4* wp = (const float4*)(w + (size_t)cc * DIM);
            float4 a0 = wp[lane * 2], a1 = wp[lane * 2 + 1];
            float s = a0.x * z0.x;
            s = fmaf(a0.y, z0.y, s); s = fmaf(a0.z, z0.z, s); s = fmaf(a0.w, z0.w, s);
            s = fmaf(a1.x, z1.x, s); s = fmaf(a1.y, z1.y, s);
            s = fmaf(a1.z, z1.z, s); s = fmaf(a1.w, z1.w, s);
#pragma unroll
            for (int off = 16; off; off >>= 1) s += __shfl_xor_sync(0xffffffffu, s, off);
            float ex = __ldg(&g_wnorm[cc]) - 2.f * s;
            unsigned long long p = ((unsigned long long)mapf(ex) << 32) | (unsigned)cc;
            if (p < best) best = p;
        }
    }
    if (lane == 0) g_best[m] = best;
}

// ---------------- K4: per-point gather / quantize / scatter EMA ----------------
__global__ void assign_kernel(const float* __restrict__ z, const float* __restrict__ w,
                              float* __restrict__ out_zq, float* __restrict__ out_idx,
                              float* __restrict__ out_ea) {
    int warp = (blockIdx.x * blockDim.x + threadIdx.x) >> 5;
    int lane = threadIdx.x & 31;
    if (warp >= NP) return;
    unsigned long long b = g_best[warp];
    int idx = (int)(unsigned)(b & 0xFFFFFFFFull);
    const float4* zp = (const float4*)(z + (size_t)warp * DIM);
    const float4* wp = (const float4*)(w + (size_t)idx * DIM);
    float4* oq = (float4*)(out_zq + (size_t)warp * DIM);
    float* ea = out_ea + (size_t)idx * DIM;
    float local = 0.f;
#pragma unroll
    for (int it = 0; it < 2; it++) {
        int v = lane + it * 32;
        float4 zv = zp[v];
        float4 wv = wp[v];
        float dx = wv.x - zv.x, dy = wv.y - zv.y, dz = wv.z - zv.z, dw = wv.w - zv.w;
        float4 o; o.x = zv.x + dx; o.y = zv.y + dy; o.z = zv.z + dz; o.w = zv.w + dw;
        oq[v] = o;
        local += dx * dx + dy * dy + dz * dz + dw * dw;
        int d = v * 4;
        atomicAdd(&ea[d + 0], OMDECAYF * zv.x);
        atomicAdd(&ea[d + 1], OMDECAYF * zv.y);
        atomicAdd(&ea[d + 2], OMDECAYF * zv.z);
        atomicAdd(&ea[d + 3], OMDECAYF * zv.w);
    }
#pragma unroll
    for (int off = 16; off; off >>= 1) local += __shfl_xor_sync(0xffffffffu, local, off);
    if (lane == 0) {
        g_ptloss[warp] = local;
        out_idx[warp] = (float)idx;
        atomicAdd(&g_counts[idx], 1.0f);
    }
}

// ---------------- K5: cs + deterministic reductions (merged) ----------------
__global__ void reduce_kernel(const float* __restrict__ cs_in, float* __restrict__ out_cs,
                              float* __restrict__ out_loss) {
    __shared__ float sm[1024];
    int t = threadIdx.x;
    float s = 0.f;
    for (int i = t; i < NC; i += 1024) {
        float v = DECAYF * cs_in[i] + OMDECAYF * g_counts[i];
        out_cs[i] = v;
        s += v;
    }
    sm[t] = s; __syncthreads();
    for (int off = 512; off; off >>= 1) { if (t < off) sm[t] += sm[t + off]; __syncthreads(); }
    if (t == 0) g_n = sm[0];
    __syncthreads();
    float l = 0.f;
    for (int i = t; i < NP; i += 1024) l += g_ptloss[i];
    sm[t] = l; __syncthreads();
    for (int off = 512; off; off >>= 1) { if (t < off) sm[t] += sm[t + off]; __syncthreads(); }
    if (t == 0) out_loss[0] = sm[0] * (1.f / (float)(NP * DIM));
}

// ---------------- K6: new weight ----------------
__global__ void weight_kernel(const float* __restrict__ out_ea, const float* __restrict__ out_cs,
                              float* __restrict__ out_w) {
    int i = blockIdx.x * blockDim.x + threadIdx.x;
    if (i >= NC * DIM) return;
    int k = i >> 8;
    float n = g_n;
    float denom = (out_cs[k] + EPSF) / (n + (float)NC * EPSF) * n;
    out_w[i] = out_ea[i] / denom;
}

// ---------------- launch ----------------
extern "C" void kernel_launch(void* const* d_in, const int* in_sizes, int n_in,
                              void* d_out, int out_size) {
    const float* z  = (const float*)d_in[0];
    const float* w  = (const float*)d_in[1];
    const float* cs = (const float*)d_in[2];
    const float* ea = (const float*)d_in[3];
    float* out = (float*)d_out;
    float* out_zq   = out;
    float* out_loss = out + (size_t)NP * DIM;
    float* out_idx  = out_loss + 1;
    float* out_w    = out_idx + NP;
    float* out_cs   = out_w + (size_t)NC * DIM;
    float* out_ea   = out_cs + NC;

    constexpr int SMEM_GEMM = 2048 + STAGES * STAGE_B;   // 2048 + 92160 = 94208
    cudaFuncSetAttribute(mma_gemm_approx, cudaFuncAttributeMaxDynamicSharedMemorySize, SMEM_GEMM);

    prep_kernel<<<(NP * DIM + 1023) / 1024, 1024>>>(z, w, ea, out_ea);
    wnorm_kernel<<<NC * 32 / 256, 256>>>(w);
    dim3 g(NP / BM, NC / BN);
    mma_gemm_approx<<<g, NTHREADS, SMEM_GEMM>>>();
    refine_kernel<<<NP / 8, 256>>>(z, w);
    assign_kernel<<<NP * 32 / 256, 256>>>(z, w, out_zq, out_idx, out_ea);
    reduce_kernel<<<1, 1024>>>(cs, out_cs, out_loss);
    weight_kernel<<<(NC * DIM + 1023) / 1024, 1024>>>(out_ea, out_cs, out_w);
}

// round 15
// speedup vs baseline: 1.6528x; 1.6528x over previous
#include <cuda_runtime.h>
#include <cuda_fp16.h>
#include <cstdint>

#define NP 16384      // number of z vectors (16*32*32)
#define NC 8192       // codebook size
#define DIM 256       // embedding dim
#define DECAYF 0.99f
#define OMDECAYF 0.01f
#define EPSF 1e-5f
#define MARGIN 6.0f

// GEMM tiling: BM=128, BN=128, 8 warps (2x4), warp tile 64x32, fp16 accum, 2 CTAs/SM
#define BM 128
#define BN 128
#define BK 32
#define NCHUNK (DIM / BK)      // 8
#define STAGES 3
#define ROWB 80
#define A_TILE_B (BM * ROWB)   // 10240
#define B_TILE_B (BN * ROWB)   // 10240
#define STAGE_B (A_TILE_B + B_TILE_B)   // 20480
#define NTHREADS 256
#define NTILE (NC / BN)        // 64 column tiles

// ---------------- scratch (no allocation allowed) ----------------
__device__ unsigned long long g_best[NP];
__device__ unsigned g_amin[NP];                     // global approx row min (mapped)
__device__ unsigned g_tilemin[(size_t)NP * NTILE];  // per 128-col tile row min (mapped)
__device__ float g_wnorm[NC];
__device__ float g_counts[NC];
__device__ float g_ptloss[NP];
__device__ float g_n;
__device__ __align__(256) __half g_zh[NP * DIM];
__device__ __align__(256) __half g_wh[NC * DIM];
__device__ __align__(256) __half g_dots[(size_t)NP * NC];   // 256 MB approx dots

// ---------------- PTX helpers ----------------
__device__ __forceinline__ uint32_t smem_u32(const void* p) {
    uint32_t a;
    asm("{ .reg .u64 t; cvta.to.shared.u64 t, %1; cvt.u32.u64 %0, t; }" : "=r"(a) : "l"(p));
    return a;
}
__device__ __forceinline__ void cp16(uint32_t dst, const void* src) {
    asm volatile("cp.async.cg.shared.global [%0], [%1], 16;" :: "r"(dst), "l"(src) : "memory");
}
#define CP_COMMIT() asm volatile("cp.async.commit_group;" ::: "memory")
#define CP_WAIT1()  asm volatile("cp.async.wait_group 1;" ::: "memory")
#define CP_WAIT0()  asm volatile("cp.async.wait_group 0;" ::: "memory")

__device__ __forceinline__ void ldm_x4(uint32_t* r, uint32_t addr) {
    asm volatile("ldmatrix.sync.aligned.m8n8.x4.shared.b16 {%0,%1,%2,%3}, [%4];"
        : "=r"(r[0]), "=r"(r[1]), "=r"(r[2]), "=r"(r[3]) : "r"(addr));
}
__device__ __forceinline__ void mma16816h(uint32_t* c, const uint32_t* a, const uint32_t* b) {
    asm volatile(
        "mma.sync.aligned.m16n8k16.row.col.f16.f16.f16.f16 "
        "{%0,%1}, {%2,%3,%4,%5}, {%6,%7}, {%0,%1};"
        : "+r"(c[0]), "+r"(c[1])
        : "r"(a[0]), "r"(a[1]), "r"(a[2]), "r"(a[3]), "r"(b[0]), "r"(b[1]));
}
__device__ __forceinline__ unsigned mapf(float f) {
    unsigned u = __float_as_uint(f);
    return (u & 0x80000000u) ? ~u : (u | 0x80000000u);
}
__device__ __forceinline__ float unmapf(unsigned v) {
    return __uint_as_float((v & 0x80000000u) ? (v & 0x7FFFFFFFu) : ~v);
}

// ---------------- K0: prep — init + fp16 conversion (merged) ----------------
__global__ void prep_kernel(const float* __restrict__ z, const float* __restrict__ w,
                            const float* __restrict__ ea_in, float* __restrict__ out_ea) {
    int i = blockIdx.x * blockDim.x + threadIdx.x;
    if (i < NP * DIM) g_zh[i] = __float2half_rn(z[i]);
    if (i < NC * DIM) {
        g_wh[i] = __float2half_rn(w[i]);
        out_ea[i] = DECAYF * ea_in[i];
    }
    if (i < NP) g_amin[i] = 0xFFFFFFFFu;
    if (i < NC) g_counts[i] = 0.f;
}

// ---------------- K1: per-code squared norms (fp32 exact) ----------------
__global__ void wnorm_kernel(const float* __restrict__ w) {
    int warp = (blockIdx.x * blockDim.x + threadIdx.x) >> 5;
    int lane = threadIdx.x & 31;
    if (warp >= NC) return;
    const float4* row = (const float4*)(w + (size_t)warp * DIM);
    float s = 0.f;
#pragma unroll
    for (int it = 0; it < 2; it++) {
        float4 v = row[lane + it * 32];
        s += v.x * v.x + v.y * v.y + v.z * v.z + v.w * v.w;
    }
#pragma unroll
    for (int off = 16; off; off >>= 1) s += __shfl_xor_sync(0xffffffffu, s, off);
    if (lane == 0) g_wnorm[warp] = s;
}

// ---------------- K2: fp16-acc mma GEMM -> fp16 dots + row/tile minima ----------------
__global__ __launch_bounds__(NTHREADS, 2) void mma_gemm_approx() {
    extern __shared__ char smem[];
    const uint32_t sb = smem_u32(smem);
    const int tid = threadIdx.x, wid = tid >> 5, lane = tid & 31;
    const int warp_m = wid >> 2, warp_n = wid & 3;   // 2 x 4 warps
    const int m0 = blockIdx.x * BM, n0 = blockIdx.y * BN;

    unsigned* rowmin = (unsigned*)smem;              // 128 u32 @ [0,512)
    float* wns = (float*)(smem + 512);               // 128 f32 @ [512,1024)
    constexpr uint32_t OFF_STAGE = 1024;

    if (tid < BM) rowmin[tid] = 0xFFFFFFFFu;
    if (tid < BN) wns[tid] = g_wnorm[n0 + tid];

    auto load_stage = [&](int chunk, int stg) {
        const uint32_t stage = sb + OFF_STAGE + stg * STAGE_B;
#pragma unroll
        for (int r = 0; r < 4; r++) {
            int idx = tid + r * NTHREADS;            // 0..1023
            if (idx < 512) {
                int row = idx >> 2, cj = idx & 3;
                const __half* src = g_zh + (size_t)(m0 + row) * DIM + chunk * BK + cj * 8;
                cp16(stage + row * ROWB + cj * 16, src);
            } else {
                int q = idx - 512;
                int row = q >> 2, cj = q & 3;
                const __half* src = g_wh + (size_t)(n0 + row) * DIM + chunk * BK + cj * 8;
                cp16(stage + A_TILE_B + row * ROWB + cj * 16, src);
            }
        }
    };

    load_stage(0, 0); CP_COMMIT();
    load_stage(1, 1); CP_COMMIT();

    uint32_t c[4][4][2] = {};    // [mt][nt][2]  fp16x2 accum, 64x32 warp tile

    for (int ch = 0; ch < NCHUNK; ch++) {
        if (ch == NCHUNK - 1) { CP_WAIT0(); } else { CP_WAIT1(); }
        __syncthreads();
        if (ch + 2 < NCHUNK) { load_stage(ch + 2, (ch + 2) % STAGES); CP_COMMIT(); }

        const uint32_t stage = sb + OFF_STAGE + (ch % STAGES) * STAGE_B;
        const uint32_t sA = stage, sB = stage + A_TILE_B;

#pragma unroll
        for (int s = 0; s < 2; s++) {
            const uint32_t acol = s * 32 + ((lane >> 4) << 4);
            const int arow = lane & 15;
            uint32_t ah[4][4];
#pragma unroll
            for (int mt = 0; mt < 4; mt++)
                ldm_x4(ah[mt], sA + (uint32_t)(warp_m * 64 + mt * 16 + arow) * ROWB + acol);
            const int brow = ((lane >> 4) << 3) + (lane & 7);
            const uint32_t bcol = s * 32 + ((lane >> 3) & 1) * 16;
            uint32_t bh[2][4];
#pragma unroll
            for (int nt2 = 0; nt2 < 2; nt2++)
                ldm_x4(bh[nt2], sB + (uint32_t)(warp_n * 32 + nt2 * 16 + brow) * ROWB + bcol);
#pragma unroll
            for (int mt = 0; mt < 4; mt++)
#pragma unroll
                for (int nt = 0; nt < 4; nt++)
                    mma16816h(c[mt][nt], ah[mt], &bh[nt >> 1][(nt & 1) * 2]);
        }
    }

    // ---- epilogue: store fp16 dots + per-row minima into smem ----
    const int rbase = warp_m * 64 + (lane >> 2);
    const int lcol0 = warp_n * 32 + 2 * (lane & 3);
#pragma unroll
    for (int mt = 0; mt < 4; mt++) {
        const int r0 = rbase + mt * 16;
        unsigned best0 = 0xFFFFFFFFu, best1 = 0xFFFFFFFFu;
#pragma unroll
        for (int nt = 0; nt < 4; nt++) {
            const int col = lcol0 + nt * 8;
            __stcs((uint32_t*)((unsigned short*)g_dots + (size_t)(m0 + r0) * NC + n0 + col), c[mt][nt][0]);
            __stcs((uint32_t*)((unsigned short*)g_dots + (size_t)(m0 + r0 + 8) * NC + n0 + col), c[mt][nt][1]);
            float2 d0 = __half22float2(*(__half2*)&c[mt][nt][0]);
            float2 d1 = __half22float2(*(__half2*)&c[mt][nt][1]);
            float w0 = wns[col], w1 = wns[col + 1];
            best0 = min(best0, min(mapf(w0 - 2.f * d0.x), mapf(w1 - 2.f * d0.y)));
            best1 = min(best1, min(mapf(w0 - 2.f * d1.x), mapf(w1 - 2.f * d1.y)));
        }
#pragma unroll
        for (int off = 1; off < 4; off <<= 1) {
            best0 = min(best0, __shfl_xor_sync(0xffffffffu, best0, off));
            best1 = min(best1, __shfl_xor_sync(0xffffffffu, best1, off));
        }
        if ((lane & 3) == 0) {
            atomicMin(&rowmin[r0], best0);
            atomicMin(&rowmin[r0 + 8], best1);
        }
    }
    __syncthreads();
    if (tid < BM) {
        unsigned v = rowmin[tid];
        atomicMin(&g_amin[m0 + tid], v);
        g_tilemin[(size_t)(m0 + tid) * NTILE + blockIdx.y] = v;
    }
}

// ---------------- K3: tile-min-guided scan + exact fp32 refine ----------------
__global__ __launch_bounds__(256) void scan_kernel(const float* __restrict__ z,
                                                   const float* __restrict__ w) {
    const int tid = threadIdx.x, warp = tid >> 5, lane = tid & 31;
    const int m = blockIdx.x * 8 + warp;

    const float4* zp = (const float4*)(z + (size_t)m * DIM);
    const float4 z0 = zp[lane * 2], z1 = zp[lane * 2 + 1];
    const float thresh = unmapf(g_amin[m]) + MARGIN;
    unsigned long long best = 0xFFFFFFFFFFFFFFFFull;

    const unsigned short* drow = (const unsigned short*)(g_dots + (size_t)m * NC);
    const unsigned* tmrow = g_tilemin + (size_t)m * NTILE;

#pragma unroll
    for (int h = 0; h < 2; h++) {
        const int ny = h * 32 + lane;
        bool q = unmapf(tmrow[ny]) <= thresh;
        unsigned bal = __ballot_sync(0xffffffffu, q);
        while (bal) {
            int src = __ffs(bal) - 1; bal &= bal - 1;
            const int tile = h * 32 + src;
            const int cbase = tile * BN;
            unsigned flags = 0;
#pragma unroll
            for (int e = 0; e < 4; e++) {
                int col = cbase + e * 32 + lane;
                float d = __half2float(__ushort_as_half(__ldcs(drow + col)));
                float sc = __ldg(&g_wnorm[col]) - 2.f * d;
                flags |= (sc <= thresh) ? (1u << e) : 0u;
            }
            unsigned any = __ballot_sync(0xffffffffu, flags != 0);
            while (any) {
                int s2 = __ffs(any) - 1; any &= any - 1;
                unsigned f = __shfl_sync(0xffffffffu, flags, s2);
                while (f) {
                    int e = __ffs(f) - 1; f &= f - 1;
                    int cc = cbase + e * 32 + s2;
                    const float4* wp = (const float4*)(w + (size_t)cc * DIM);
                    float4 a0 = wp[lane * 2], a1 = wp[lane * 2 + 1];
                    float s = a0.x * z0.x;
                    s = fmaf(a0.y, z0.y, s); s = fmaf(a0.z, z0.z, s); s = fmaf(a0.w, z0.w, s);
                    s = fmaf(a1.x, z1.x, s); s = fmaf(a1.y, z1.y, s);
                    s = fmaf(a1.z, z1.z, s); s = fmaf(a1.w, z1.w, s);
#pragma unroll
                    for (int off = 16; off; off >>= 1) s += __shfl_xor_sync(0xffffffffu, s, off);
                    float ex = __ldg(&g_wnorm[cc]) - 2.f * s;
                    unsigned long long p = ((unsigned long long)mapf(ex) << 32) | (unsigned)cc;
                    if (p < best) best = p;
                }
            }
        }
    }
    if (lane == 0) g_best[m] = best;
}

// ---------------- K4: per-point gather / quantize / scatter EMA ----------------
__global__ void assign_kernel(const float* __restrict__ z, const float* __restrict__ w,
                              float* __restrict__ out_zq, float* __restrict__ out_idx,
                              float* __restrict__ out_ea) {
    int warp = (blockIdx.x * blockDim.x + threadIdx.x) >> 5;
    int lane = threadIdx.x & 31;
    if (warp >= NP) return;
    unsigned long long b = g_best[warp];
    int idx = (int)(unsigned)(b & 0xFFFFFFFFull);
    const float4* zp = (const float4*)(z + (size_t)warp * DIM);
    const float4* wp = (const float4*)(w + (size_t)idx * DIM);
    float4* oq = (float4*)(out_zq + (size_t)warp * DIM);
    float* ea = out_ea + (size_t)idx * DIM;
    float local = 0.f;
#pragma unroll
    for (int it = 0; it < 2; it++) {
        int v = lane + it * 32;
        float4 zv = zp[v];
        float4 wv = wp[v];
        float dx = wv.x - zv.x, dy = wv.y - zv.y, dz = wv.z - zv.z, dw = wv.w - zv.w;
        float4 o; o.x = zv.x + dx; o.y = zv.y + dy; o.z = zv.z + dz; o.w = zv.w + dw;
        oq[v] = o;
        local += dx * dx + dy * dy + dz * dz + dw * dw;
        int d = v * 4;
        atomicAdd(&ea[d + 0], OMDECAYF * zv.x);
        atomicAdd(&ea[d + 1], OMDECAYF * zv.y);
        atomicAdd(&ea[d + 2], OMDECAYF * zv.z);
        atomicAdd(&ea[d + 3], OMDECAYF * zv.w);
    }
#pragma unroll
    for (int off = 16; off; off >>= 1) local += __shfl_xor_sync(0xffffffffu, local, off);
    if (lane == 0) {
        g_ptloss[warp] = local;
        out_idx[warp] = (float)idx;
        atomicAdd(&g_counts[idx], 1.0f);
    }
}

// ---------------- K5: cs + deterministic reductions (merged) ----------------
__global__ void reduce_kernel(const float* __restrict__ cs_in, float* __restrict__ out_cs,
                              float* __restrict__ out_loss) {
    __shared__ float sm[1024];
    int t = threadIdx.x;
    float s = 0.f;
    for (int i = t; i < NC; i += 1024) {
        float v = DECAYF * cs_in[i] + OMDECAYF * g_counts[i];
        out_cs[i] = v;
        s += v;
    }
    sm[t] = s; __syncthreads();
    for (int off = 512; off; off >>= 1) { if (t < off) sm[t] += sm[t + off]; __syncthreads(); }
    if (t == 0) g_n = sm[0];
    __syncthreads();
    float l = 0.f;
    for (int i = t; i < NP; i += 1024) l += g_ptloss[i];
    sm[t] = l; __syncthreads();
    for (int off = 512; off; off >>= 1) { if (t < off) sm[t] += sm[t + off]; __syncthreads(); }
    if (t == 0) out_loss[0] = sm[0] * (1.f / (float)(NP * DIM));
}

// ---------------- K6: new weight ----------------
__global__ void weight_kernel(const float* __restrict__ out_ea, const float* __restrict__ out_cs,
                              float* __restrict__ out_w) {
    int i = blockIdx.x * blockDim.x + threadIdx.x;
    if (i >= NC * DIM) return;
    int k = i >> 8;
    float n = g_n;
    float denom = (out_cs[k] + EPSF) / (n + (float)NC * EPSF) * n;
    out_w[i] = out_ea[i] / denom;
}

// ---------------- launch ----------------
extern "C" void kernel_launch(void* const* d_in, const int* in_sizes, int n_in,
                              void* d_out, int out_size) {
    const float* z  = (const float*)d_in[0];
    const float* w  = (const float*)d_in[1];
    const float* cs = (const float*)d_in[2];
    const float* ea = (const float*)d_in[3];
    float* out = (float*)d_out;
    float* out_zq   = out;
    float* out_loss = out + (size_t)NP * DIM;
    float* out_idx  = out_loss + 1;
    float* out_w    = out_idx + NP;
    float* out_cs   = out_w + (size_t)NC * DIM;
    float* out_ea   = out_cs + NC;

    constexpr int SMEM_GEMM = 1024 + STAGES * STAGE_B;   // 1024 + 61440 = 62464
    cudaFuncSetAttribute(mma_gemm_approx, cudaFuncAttributeMaxDynamicSharedMemorySize, SMEM_GEMM);

    prep_kernel<<<(NP * DIM + 1023) / 1024, 1024>>>(z, w, ea, out_ea);
    wnorm_kernel<<<NC * 32 / 256, 256>>>(w);
    dim3 g(NP / BM, NC / BN);
    mma_gemm_approx<<<g, NTHREADS, SMEM_GEMM>>>();
    scan_kernel<<<NP / 8, 256>>>(z, w);
    assign_kernel<<<NP * 32 / 256, 256>>>(z, w, out_zq, out_idx, out_ea);
    reduce_kernel<<<1, 1024>>>(cs, out_cs, out_loss);
    weight_kernel<<<(NC * DIM + 1023) / 1024, 1024>>>(out_ea, out_cs, out_w);
}

// round 16
// speedup vs baseline: 1.6950x; 1.0255x over previous
#include <cuda_runtime.h>
#include <cuda_fp16.h>
#include <cstdint>

#define NP 16384      // number of z vectors (16*32*32)
#define NC 8192       // codebook size
#define DIM 256       // embedding dim
#define DECAYF 0.99f
#define OMDECAYF 0.01f
#define EPSF 1e-5f
#define MARGIN 6.0f

// GEMM tiling: BM=128, BN=128, 8 warps (2x4), warp tile 64x32, fp16 accum, 3 CTAs/SM
#define BM 128
#define BN 128
#define BK 32
#define NCHUNK (DIM / BK)      // 8
#define STAGES 3
#define ROWB 80
#define A_TILE_B (BM * ROWB)   // 10240
#define B_TILE_B (BN * ROWB)   // 10240
#define STAGE_B (A_TILE_B + B_TILE_B)   // 20480
#define NTHREADS 256
#define NTILE (NC / BN)        // 64 column tiles

// ---------------- scratch (no allocation allowed) ----------------
__device__ unsigned long long g_best[NP];
__device__ unsigned g_amin[NP];                     // global approx row min (mapped)
__device__ unsigned g_tilemin[(size_t)NP * NTILE];  // per 128-col tile row min (mapped)
__device__ float g_wnorm[NC];
__device__ float g_counts[NC];
__device__ float g_ptloss[NP];
__device__ float g_n;
__device__ __align__(256) __half g_zh[NP * DIM];
__device__ __align__(256) __half g_wh[NC * DIM];
__device__ __align__(256) __half g_dots[(size_t)NP * NC];   // 256 MB approx dots

// ---------------- PTX helpers ----------------
__device__ __forceinline__ uint32_t smem_u32(const void* p) {
    uint32_t a;
    asm("{ .reg .u64 t; cvta.to.shared.u64 t, %1; cvt.u32.u64 %0, t; }" : "=r"(a) : "l"(p));
    return a;
}
__device__ __forceinline__ void cp16(uint32_t dst, const void* src) {
    asm volatile("cp.async.cg.shared.global [%0], [%1], 16;" :: "r"(dst), "l"(src) : "memory");
}
#define CP_COMMIT() asm volatile("cp.async.commit_group;" ::: "memory")
#define CP_WAIT1()  asm volatile("cp.async.wait_group 1;" ::: "memory")
#define CP_WAIT0()  asm volatile("cp.async.wait_group 0;" ::: "memory")

__device__ __forceinline__ void ldm_x4(uint32_t* r, uint32_t addr) {
    asm volatile("ldmatrix.sync.aligned.m8n8.x4.shared.b16 {%0,%1,%2,%3}, [%4];"
        : "=r"(r[0]), "=r"(r[1]), "=r"(r[2]), "=r"(r[3]) : "r"(addr));
}
__device__ __forceinline__ void mma16816h(uint32_t* c, const uint32_t* a, const uint32_t* b) {
    asm volatile(
        "mma.sync.aligned.m16n8k16.row.col.f16.f16.f16.f16 "
        "{%0,%1}, {%2,%3,%4,%5}, {%6,%7}, {%0,%1};"
        : "+r"(c[0]), "+r"(c[1])
        : "r"(a[0]), "r"(a[1]), "r"(a[2]), "r"(a[3]), "r"(b[0]), "r"(b[1]));
}
__device__ __forceinline__ unsigned mapf(float f) {
    unsigned u = __float_as_uint(f);
    return (u & 0x80000000u) ? ~u : (u | 0x80000000u);
}
__device__ __forceinline__ float unmapf(unsigned v) {
    return __uint_as_float((v & 0x80000000u) ? (v & 0x7FFFFFFFu) : ~v);
}

// ---------------- K0: prep — init + fp16 conversion + wnorm (merged) ----------------
__global__ void prep_kernel(const float* __restrict__ z, const float* __restrict__ w,
                            const float* __restrict__ ea_in, float* __restrict__ out_ea) {
    int i = blockIdx.x * blockDim.x + threadIdx.x;
    if (i < NP * DIM) g_zh[i] = __float2half_rn(z[i]);
    if (i < NC * DIM) {
        g_wh[i] = __float2half_rn(w[i]);
        out_ea[i] = DECAYF * ea_in[i];
    }
    if (i < NP) g_amin[i] = 0xFFFFFFFFu;
    if (i < NC) g_counts[i] = 0.f;
    // wnorm: first NC warps each reduce one w row (fp32 exact)
    int warp = i >> 5, lane = i & 31;
    if (warp < NC) {
        const float4* row = (const float4*)(w + (size_t)warp * DIM);
        float s = 0.f;
#pragma unroll
        for (int it = 0; it < 2; it++) {
            float4 v = row[lane + it * 32];
            s += v.x * v.x + v.y * v.y + v.z * v.z + v.w * v.w;
        }
#pragma unroll
        for (int off = 16; off; off >>= 1) s += __shfl_xor_sync(0xffffffffu, s, off);
        if (lane == 0) g_wnorm[warp] = s;
    }
}

// ---------------- K1: fp16-acc mma GEMM -> fp16 dots + row/tile minima ----------------
__global__ __launch_bounds__(NTHREADS, 3) void mma_gemm_approx() {
    extern __shared__ char smem[];
    const uint32_t sb = smem_u32(smem);
    const int tid = threadIdx.x, wid = tid >> 5, lane = tid & 31;
    const int warp_m = wid >> 2, warp_n = wid & 3;   // 2 x 4 warps
    const int m0 = blockIdx.x * BM, n0 = blockIdx.y * BN;

    unsigned* rowmin = (unsigned*)smem;              // 128 u32 @ [0,512)
    float* wns = (float*)(smem + 512);               // 128 f32 @ [512,1024)
    constexpr uint32_t OFF_STAGE = 1024;

    if (tid < BM) rowmin[tid] = 0xFFFFFFFFu;
    if (tid < BN) wns[tid] = g_wnorm[n0 + tid];

    auto load_stage = [&](int chunk, int stg) {
        const uint32_t stage = sb + OFF_STAGE + stg * STAGE_B;
#pragma unroll
        for (int r = 0; r < 4; r++) {
            int idx = tid + r * NTHREADS;            // 0..1023
            if (idx < 512) {
                int row = idx >> 2, cj = idx & 3;
                const __half* src = g_zh + (size_t)(m0 + row) * DIM + chunk * BK + cj * 8;
                cp16(stage + row * ROWB + cj * 16, src);
            } else {
                int q = idx - 512;
                int row = q >> 2, cj = q & 3;
                const __half* src = g_wh + (size_t)(n0 + row) * DIM + chunk * BK + cj * 8;
                cp16(stage + A_TILE_B + row * ROWB + cj * 16, src);
            }
        }
    };

    load_stage(0, 0); CP_COMMIT();
    load_stage(1, 1); CP_COMMIT();

    uint32_t c[4][4][2] = {};    // [mt][nt][2]  fp16x2 accum, 64x32 warp tile

    for (int ch = 0; ch < NCHUNK; ch++) {
        if (ch == NCHUNK - 1) { CP_WAIT0(); } else { CP_WAIT1(); }
        __syncthreads();
        if (ch + 2 < NCHUNK) { load_stage(ch + 2, (ch + 2) % STAGES); CP_COMMIT(); }

        const uint32_t stage = sb + OFF_STAGE + (ch % STAGES) * STAGE_B;
        const uint32_t sA = stage, sB = stage + A_TILE_B;

#pragma unroll
        for (int s = 0; s < 2; s++) {
            const uint32_t acol = s * 32 + ((lane >> 4) << 4);
            const int arow = lane & 15;
            uint32_t ah[4][4];
#pragma unroll
            for (int mt = 0; mt < 4; mt++)
                ldm_x4(ah[mt], sA + (uint32_t)(warp_m * 64 + mt * 16 + arow) * ROWB + acol);
            const int brow = ((lane >> 4) << 3) + (lane & 7);
            const uint32_t bcol = s * 32 + ((lane >> 3) & 1) * 16;
            uint32_t bh[2][4];
#pragma unroll
            for (int nt2 = 0; nt2 < 2; nt2++)
                ldm_x4(bh[nt2], sB + (uint32_t)(warp_n * 32 + nt2 * 16 + brow) * ROWB + bcol);
#pragma unroll
            for (int mt = 0; mt < 4; mt++)
#pragma unroll
                for (int nt = 0; nt < 4; nt++)
                    mma16816h(c[mt][nt], ah[mt], &bh[nt >> 1][(nt & 1) * 2]);
        }
    }

    // ---- epilogue: store fp16 dots + per-row minima into smem ----
    const int rbase = warp_m * 64 + (lane >> 2);
    const int lcol0 = warp_n * 32 + 2 * (lane & 3);
#pragma unroll
    for (int mt = 0; mt < 4; mt++) {
        const int r0 = rbase + mt * 16;
        unsigned best0 = 0xFFFFFFFFu, best1 = 0xFFFFFFFFu;
#pragma unroll
        for (int nt = 0; nt < 4; nt++) {
            const int col = lcol0 + nt * 8;
            __stcs((uint32_t*)((unsigned short*)g_dots + (size_t)(m0 + r0) * NC + n0 + col), c[mt][nt][0]);
            __stcs((uint32_t*)((unsigned short*)g_dots + (size_t)(m0 + r0 + 8) * NC + n0 + col), c[mt][nt][1]);
            float2 d0 = __half22float2(*(__half2*)&c[mt][nt][0]);
            float2 d1 = __half22float2(*(__half2*)&c[mt][nt][1]);
            float w0 = wns[col], w1 = wns[col + 1];
            best0 = min(best0, min(mapf(w0 - 2.f * d0.x), mapf(w1 - 2.f * d0.y)));
            best1 = min(best1, min(mapf(w0 - 2.f * d1.x), mapf(w1 - 2.f * d1.y)));
        }
#pragma unroll
        for (int off = 1; off < 4; off <<= 1) {
            best0 = min(best0, __shfl_xor_sync(0xffffffffu, best0, off));
            best1 = min(best1, __shfl_xor_sync(0xffffffffu, best1, off));
        }
        if ((lane & 3) == 0) {
            atomicMin(&rowmin[r0], best0);
            atomicMin(&rowmin[r0 + 8], best1);
        }
    }
    __syncthreads();
    if (tid < BM) {
        unsigned v = rowmin[tid];
        atomicMin(&g_amin[m0 + tid], v);
        g_tilemin[(size_t)(m0 + tid) * NTILE + blockIdx.y] = v;
    }
}

// ---------------- K2: tile-min-guided scan + exact fp32 refine ----------------
__global__ __launch_bounds__(256) void scan_kernel(const float* __restrict__ z,
                                                   const float* __restrict__ w) {
    const int tid = threadIdx.x, warp = tid >> 5, lane = tid & 31;
    const int m = blockIdx.x * 8 + warp;

    const float4* zp = (const float4*)(z + (size_t)m * DIM);
    const float4 z0 = zp[lane * 2], z1 = zp[lane * 2 + 1];
    const float thresh = unmapf(g_amin[m]) + MARGIN;
    unsigned long long best = 0xFFFFFFFFFFFFFFFFull;

    const unsigned short* drow = (const unsigned short*)(g_dots + (size_t)m * NC);
    const unsigned* tmrow = g_tilemin + (size_t)m * NTILE;

#pragma unroll
    for (int h = 0; h < 2; h++) {
        const int ny = h * 32 + lane;
        bool q = unmapf(tmrow[ny]) <= thresh;
        unsigned bal = __ballot_sync(0xffffffffu, q);
        while (bal) {
            int src = __ffs(bal) - 1; bal &= bal - 1;
            const int tile = h * 32 + src;
            const int cbase = tile * BN;
            unsigned flags = 0;
#pragma unroll
            for (int e = 0; e < 4; e++) {
                int col = cbase + e * 32 + lane;
                float d = __half2float(__ushort_as_half(__ldcs(drow + col)));
                float sc = __ldg(&g_wnorm[col]) - 2.f * d;
                flags |= (sc <= thresh) ? (1u << e) : 0u;
            }
            unsigned any = __ballot_sync(0xffffffffu, flags != 0);
            while (any) {
                int s2 = __ffs(any) - 1; any &= any - 1;
                unsigned f = __shfl_sync(0xffffffffu, flags, s2);
                while (f) {
                    int e = __ffs(f) - 1; f &= f - 1;
                    int cc = cbase + e * 32 + s2;
                    const float4* wp = (const float4*)(w + (size_t)cc * DIM);
                    float4 a0 = wp[lane * 2], a1 = wp[lane * 2 + 1];
                    float s = a0.x * z0.x;
                    s = fmaf(a0.y, z0.y, s); s = fmaf(a0.z, z0.z, s); s = fmaf(a0.w, z0.w, s);
                    s = fmaf(a1.x, z1.x, s); s = fmaf(a1.y, z1.y, s);
                    s = fmaf(a1.z, z1.z, s); s = fmaf(a1.w, z1.w, s);
#pragma unroll
                    for (int off = 16; off; off >>= 1) s += __shfl_xor_sync(0xffffffffu, s, off);
                    float ex = __ldg(&g_wnorm[cc]) - 2.f * s;
                    unsigned long long p = ((unsigned long long)mapf(ex) << 32) | (unsigned)cc;
                    if (p < best) best = p;
                }
            }
        }
    }
    if (lane == 0) g_best[m] = best;
}

// ---------------- K3: per-point gather / quantize / scatter EMA ----------------
__global__ void assign_kernel(const float* __restrict__ z, const float* __restrict__ w,
                              float* __restrict__ out_zq, float* __restrict__ out_idx,
                              float* __restrict__ out_ea) {
    int warp = (blockIdx.x * blockDim.x + threadIdx.x) >> 5;
    int lane = threadIdx.x & 31;
    if (warp >= NP) return;
    unsigned long long b = g_best[warp];
    int idx = (int)(unsigned)(b & 0xFFFFFFFFull);
    const float4* zp = (const float4*)(z + (size_t)warp * DIM);
    const float4* wp = (const float4*)(w + (size_t)idx * DIM);
    float4* oq = (float4*)(out_zq + (size_t)warp * DIM);
    float* ea = out_ea + (size_t)idx * DIM;
    float local = 0.f;
#pragma unroll
    for (int it = 0; it < 2; it++) {
        int v = lane + it * 32;
        float4 zv = zp[v];
        float4 wv = wp[v];
        float dx = wv.x - zv.x, dy = wv.y - zv.y, dz = wv.z - zv.z, dw = wv.w - zv.w;
        float4 o; o.x = zv.x + dx; o.y = zv.y + dy; o.z = zv.z + dz; o.w = zv.w + dw;
        oq[v] = o;
        local += dx * dx + dy * dy + dz * dz + dw * dw;
        int d = v * 4;
        atomicAdd(&ea[d + 0], OMDECAYF * zv.x);
        atomicAdd(&ea[d + 1], OMDECAYF * zv.y);
        atomicAdd(&ea[d + 2], OMDECAYF * zv.z);
        atomicAdd(&ea[d + 3], OMDECAYF * zv.w);
    }
#pragma unroll
    for (int off = 16; off; off >>= 1) local += __shfl_xor_sync(0xffffffffu, local, off);
    if (lane == 0) {
        g_ptloss[warp] = local;
        out_idx[warp] = (float)idx;
        atomicAdd(&g_counts[idx], 1.0f);
    }
}

// ---------------- K4: cs + deterministic reductions (merged) ----------------
__global__ void reduce_kernel(const float* __restrict__ cs_in, float* __restrict__ out_cs,
                              float* __restrict__ out_loss) {
    __shared__ float sm[1024];
    int t = threadIdx.x;
    float s = 0.f;
    for (int i = t; i < NC; i += 1024) {
        float v = DECAYF * cs_in[i] + OMDECAYF * g_counts[i];
        out_cs[i] = v;
        s += v;
    }
    sm[t] = s; __syncthreads();
    for (int off = 512; off; off >>= 1) { if (t < off) sm[t] += sm[t + off]; __syncthreads(); }
    if (t == 0) g_n = sm[0];
    __syncthreads();
    float l = 0.f;
    for (int i = t; i < NP; i += 1024) l += g_ptloss[i];
    sm[t] = l; __syncthreads();
    for (int off = 512; off; off >>= 1) { if (t < off) sm[t] += sm[t + off]; __syncthreads(); }
    if (t == 0) out_loss[0] = sm[0] * (1.f / (float)(NP * DIM));
}

// ---------------- K5: new weight ----------------
__global__ void weight_kernel(const float* __restrict__ out_ea, const float* __restrict__ out_cs,
                              float* __restrict__ out_w) {
    int i = blockIdx.x * blockDim.x + threadIdx.x;
    if (i >= NC * DIM) return;
    int k = i >> 8;
    float n = g_n;
    float denom = (out_cs[k] + EPSF) / (n + (float)NC * EPSF) * n;
    out_w[i] = out_ea[i] / denom;
}

// ---------------- launch ----------------
extern "C" void kernel_launch(void* const* d_in, const int* in_sizes, int n_in,
                              void* d_out, int out_size) {
    const float* z  = (const float*)d_in[0];
    const float* w  = (const float*)d_in[1];
    const float* cs = (const float*)d_in[2];
    const float* ea = (const float*)d_in[3];
    float* out = (float*)d_out;
    float* out_zq   = out;
    float* out_loss = out + (size_t)NP * DIM;
    float* out_idx  = out_loss + 1;
    float* out_w    = out_idx + NP;
    float* out_cs   = out_w + (size_t)NC * DIM;
    float* out_ea   = out_cs + NC;

    constexpr int SMEM_GEMM = 1024 + STAGES * STAGE_B;   // 1024 + 61440 = 62464
    cudaFuncSetAttribute(mma_gemm_approx, cudaFuncAttributeMaxDynamicSharedMemorySize, SMEM_GEMM);

    prep_kernel<<<(NP * DIM + 1023) / 1024, 1024>>>(z, w, ea, out_ea);
    dim3 g(NP / BM, NC / BN);
    mma_gemm_approx<<<g, NTHREADS, SMEM_GEMM>>>();
    scan_kernel<<<NP / 8, 256>>>(z, w);
    assign_kernel<<<NP * 32 / 256, 256>>>(z, w, out_zq, out_idx, out_ea);
    reduce_kernel<<<1, 1024>>>(cs, out_cs, out_loss);
    weight_kernel<<<(NC * DIM + 1023) / 1024, 1024>>>(out_ea, out_cs, out_w);
}